// round 4
// baseline (speedup 1.0000x reference)
#include <cuda_runtime.h>
#include <cuda_bf16.h>

// Problem constants (fixed by the dataset): B=32, L=256, V=50000, C=128
#define CC   128
#define LL   256
#define BDIM 256

__global__ __launch_bounds__(BDIM, 1)
void crf_fwd_kernel(const int*   __restrict__ tokens,
                    const int*   __restrict__ target,
                    const float* __restrict__ mask,
                    const float* __restrict__ st,      // state_table [V, C]
                    const float* __restrict__ trans,   // trans_matrix [C, C]
                    float*       __restrict__ out)     // [B]
{
    // a_s: exp(part - h), double buffered; padded so the two 64-float halves
    // start 68 floats apart (bank-disjoint for the dual-broadcast float4 reads).
    __shared__ float a_s[2][136];
    __shared__ float h_s[2];
    __shared__ int   tok_s[LL];
    __shared__ float m_s[LL];
    __shared__ float red_s[8];    // block reduce scratch (max / expsum)
    __shared__ float red2_s[8];   // block reduce scratch (target energy)
    __shared__ float bcast;

    const int b    = blockIdx.x;
    const int tid  = threadIdx.x;
    const int w    = tid >> 5;
    const int l    = tid & 31;
    const int j    = w * 16 + (l & 15);   // state index, 0..127 (each j owned by 2 lanes)
    const int half = l >> 4;              // which half of the i-dimension this lane sums

    // ---- prologue: stage tokens/mask, compute target-path energy partial ----
    tok_s[tid] = tokens[b * LL + tid];
    m_s[tid]   = mask[b * LL + tid];

    float tgt_part;
    {
        const int t    = tid;                                  // BDIM == LL
        const int tg   = target[b * LL + t];
        const int prev = (t == 0) ? (CC - 1) : target[b * LL + t - 1];
        const int tok  = tokens[b * LL + t];
        tgt_part = (trans[prev * CC + tg] + st[tok * CC + tg]) * mask[b * LL + t];
    }

    // ---- E = exp(trans) column slice in registers: E[k] = exp(trans[half*64+k][j]) ----
    float E[64];
#pragma unroll
    for (int k = 0; k < 64; ++k)
        E[k] = __expf(trans[(half * 64 + k) * CC + j]);

    __syncthreads();

    // ---- init: part0[j] = (trans[C-1][j] + em[0][j]) * mask[0] ----
    const float m0 = m_s[0];
    float r = (trans[(CC - 1) * CC + j] + st[tok_s[0] * CC + j]) * m0;
    float S = 0.0f;   // accumulated shift; true part[j] = r + S
    float h = 0.0f;   // shift applied at exp time (lagged r[0])

    // emission prefetch pipeline (depth 2)
    float em_cur = st[tok_s[1] * CC + j];
    float em_n1  = st[tok_s[2] * CC + j];

    // write index for a_s with the 4-float pad between halves
    const int sj = j + ((j >> 6) << 2);

    // ---- sequential scan: one __syncthreads per step ----
    for (int t = 1; t < LL; ++t) {
        const int buf = t & 1;

        const float a = __expf(r - h);
        a_s[buf][sj] = a;              // both owner lanes write the same value
        if (tid == 0) h_s[buf] = r;    // publish r[0] -> shift for NEXT step
        S += h;
        __syncthreads();

        const float h_next = h_s[buf];

        // prefetch emission row for step t+2
        float em_n2 = 0.0f;
        if (t + 2 < LL) em_n2 = __ldg(&st[tok_s[t + 2] * CC + j]);

        // exp-domain matvec: s_half = sum_k a[half*64+k] * E[k]
        const float* ap = &a_s[buf][half * 68];
        float s0 = 0.f, s1 = 0.f, s2 = 0.f, s3 = 0.f;
#pragma unroll
        for (int k = 0; k < 64; k += 4) {
            const float4 av = *reinterpret_cast<const float4*>(ap + k);
            s0 = fmaf(av.x, E[k + 0], s0);
            s1 = fmaf(av.y, E[k + 1], s1);
            s2 = fmaf(av.z, E[k + 2], s2);
            s3 = fmaf(av.w, E[k + 3], s3);
        }
        float s = (s0 + s1) + (s2 + s3);
        s += __shfl_xor_sync(0xffffffffu, s, 16);   // combine the two halves (same warp)

        const float mt   = m_s[t];
        const float cand = fmaf(em_cur, mt, __logf(s));     // em*m + log(sum)
        // masked blend in shifted domain (exact for m in {0,1}):
        //   r' = (r - h) + (cand + h - r) * m ;  S' = S + h (already added above)
        r = (r - h) + (cand + h - r) * mt;

        h = h_next;
        em_cur = em_n1;
        em_n1  = em_n2;
    }

    // ---- epilogue: loss = S + logsumexp_j(r) - tgt_energy ----
    // block max over r (redundant lanes hold identical values; max unaffected)
    float pm = r;
#pragma unroll
    for (int o = 16; o; o >>= 1) pm = fmaxf(pm, __shfl_xor_sync(0xffffffffu, pm, o));
    if (l == 0) red_s[w] = pm;

    // warp-sum the target-energy partials (all 256 t's distinct)
    float tp = tgt_part;
#pragma unroll
    for (int o = 16; o; o >>= 1) tp += __shfl_xor_sync(0xffffffffu, tp, o);
    if (l == 0) red2_s[w] = tp;
    __syncthreads();

    if (tid == 0) {
        float mm = red_s[0];
#pragma unroll
        for (int i = 1; i < 8; ++i) mm = fmaxf(mm, red_s[i]);
        bcast = mm;
    }
    __syncthreads();
    pm = bcast;

    // sum exp(r - pm), counting each state once (half==0 lanes only)
    float e = (half == 0) ? __expf(r - pm) : 0.0f;
#pragma unroll
    for (int o = 16; o; o >>= 1) e += __shfl_xor_sync(0xffffffffu, e, o);
    if (l == 0) red_s[w] = e;
    __syncthreads();

    if (tid == 0) {
        float ssum = 0.f, tsum = 0.f;
#pragma unroll
        for (int i = 0; i < 8; ++i) { ssum += red_s[i]; tsum += red2_s[i]; }
        out[b] = S + pm + logf(ssum) - tsum;
    }
}

extern "C" void kernel_launch(void* const* d_in, const int* in_sizes, int n_in,
                              void* d_out, int out_size)
{
    const int*   tokens = (const int*)  d_in[0];
    const int*   target = (const int*)  d_in[1];
    const float* mask   = (const float*)d_in[2];
    const float* st     = (const float*)d_in[3];
    const float* trans  = (const float*)d_in[4];
    float*       out    = (float*)d_out;

    const int B = in_sizes[0] / LL;   // 32
    crf_fwd_kernel<<<B, BDIM>>>(tokens, target, mask, st, trans, out);
}